// round 2
// baseline (speedup 1.0000x reference)
#include <cuda_runtime.h>
#include <cstdint>

// ESMGridSample: bilinear grid_sample, zeros padding, align_corners=False.
// img:  [16, 1, 1024, 1024] f32   (d_in[0])
// grid: [16, 1024, 1024, 2] f32   (d_in[1])  (x, y) in [-1, 1]-ish
// gt_map (d_in[2]) unused.
// out:  [16, 1, 1024, 1024] f32
//
// ix = (x + 1) * 512 - 0.5 = fma(x, 512, 511.5); same for iy.
// 4-tap gather with zero padding outside [0,1024).

#define HW_SHIFT 20           // 1024*1024 elements per batch image
#define DIM 1024
#define TOTAL (16u * 1024u * 1024u)

__global__ __launch_bounds__(256) void esm_grid_sample_kernel(
    const float* __restrict__ img,
    const float* __restrict__ grid,
    float* __restrict__ out)
{
    // Each thread produces 4 consecutive output pixels (same batch: HW % 4 == 0).
    unsigned tid = blockIdx.x * blockDim.x + threadIdx.x;
    unsigned p0 = tid * 4u;                 // linear output index of first pixel
    if (p0 >= TOTAL) return;

    unsigned n = p0 >> HW_SHIFT;            // batch
    const float* __restrict__ base = img + ((size_t)n << HW_SHIFT);

    // Grid: 2 floats per pixel -> 8 floats for 4 pixels, aligned to 32 B.
    const float4* __restrict__ g4 = (const float4*)(grid + (size_t)p0 * 2u);
    float4 ga = g4[0];   // (x0,y0,x1,y1)
    float4 gb = g4[1];   // (x2,y2,x3,y3)

    float xs[4] = {ga.x, ga.z, gb.x, gb.z};
    float ys[4] = {ga.y, ga.w, gb.y, gb.w};

    float res[4];

    #pragma unroll
    for (int i = 0; i < 4; ++i) {
        float ix = fmaf(xs[i], 512.0f, 511.5f);
        float iy = fmaf(ys[i], 512.0f, 511.5f);
        float x0f = floorf(ix);
        float y0f = floorf(iy);
        float wx = ix - x0f;
        float wy = iy - y0f;
        int x0 = (int)x0f;
        int y0 = (int)y0f;

        bool xv0 = (unsigned)x0 < (unsigned)DIM;
        bool xv1 = (unsigned)(x0 + 1) < (unsigned)DIM;
        bool yv0 = (unsigned)y0 < (unsigned)DIM;
        bool yv1 = (unsigned)(y0 + 1) < (unsigned)DIM;

        // Clamp for address safety; validity mask applied to value.
        int xc0 = min(max(x0, 0), DIM - 1);
        int xc1 = min(max(x0 + 1, 0), DIM - 1);
        int yc0 = min(max(y0, 0), DIM - 1);
        int yc1 = min(max(y0 + 1, 0), DIM - 1);

        const float* r0 = base + ((unsigned)yc0 << 10);
        const float* r1 = base + ((unsigned)yc1 << 10);

        float v00 = (xv0 & yv0) ? __ldg(r0 + xc0) : 0.0f;
        float v01 = (xv1 & yv0) ? __ldg(r0 + xc1) : 0.0f;
        float v10 = (xv0 & yv1) ? __ldg(r1 + xc0) : 0.0f;
        float v11 = (xv1 & yv1) ? __ldg(r1 + xc1) : 0.0f;

        float top = fmaf(v01 - v00, wx, v00);   // v00*(1-wx) + v01*wx
        float bot = fmaf(v11 - v10, wx, v10);
        res[i] = fmaf(bot - top, wy, top);
    }

    float4 o;
    o.x = res[0]; o.y = res[1]; o.z = res[2]; o.w = res[3];
    *(float4*)(out + (size_t)p0) = o;
}

extern "C" void kernel_launch(void* const* d_in, const int* in_sizes, int n_in,
                              void* d_out, int out_size)
{
    const float* img  = (const float*)d_in[0];   // source_depth
    const float* grid = (const float*)d_in[1];   // pr
    // d_in[2] (gt_map) unused.
    float* out = (float*)d_out;

    const unsigned threads = 256;
    const unsigned total_thr = TOTAL / 4u;       // 4 pixels per thread
    const unsigned blocks = (total_thr + threads - 1) / threads;
    esm_grid_sample_kernel<<<blocks, threads>>>(img, grid, out);
}

// round 3
// speedup vs baseline: 1.1874x; 1.1874x over previous
#include <cuda_runtime.h>
#include <cstdint>

// ESMGridSample: bilinear grid_sample, zeros padding, align_corners=False.
// img:  [16, 1, 1024, 1024] f32   (d_in[0])
// grid: [16, 1024, 1024, 2] f32   (d_in[1])  (x, y) roughly in [-1.05, 1.05]
// gt_map (d_in[2]) unused.
// out:  [16, 1, 1024, 1024] f32
//
// Optimization vs R1: the two horizontal taps (x0, x0+1) of each row are
// fetched with ONE aligned LDG.128 (the float4 quad containing x0) instead of
// two scalar gathers. 75% of the time both taps are inside the quad; the
// remaining 25% (x0 % 4 == 3) issue one predicated scalar LDG.32 for x0+1.
// This cuts L1tex wavefronts and L2 sector requests from 4/pixel to 2.5/pixel.

#define HW_SHIFT 20           // 1024*1024 elements per batch image
#define DIM 1024
#define TOTAL (16u * 1024u * 1024u)

__device__ __forceinline__ float pick4(float4 q, int idx) {
    // idx in [0,3]; 3 selects, fma/alu pipes have huge headroom.
    float a = (idx & 2) ? q.z : q.x;
    float b = (idx & 2) ? q.w : q.y;
    return (idx & 1) ? b : a;
}

__global__ __launch_bounds__(256) void esm_grid_sample_kernel(
    const float* __restrict__ img,
    const float* __restrict__ grid,
    float* __restrict__ out)
{
    // Each thread produces 4 consecutive output pixels (same batch: HW % 4 == 0).
    unsigned tid = blockIdx.x * blockDim.x + threadIdx.x;
    unsigned p0 = tid * 4u;                 // linear output index of first pixel
    if (p0 >= TOTAL) return;

    unsigned n = p0 >> HW_SHIFT;            // batch
    const float* __restrict__ base = img + ((size_t)n << HW_SHIFT);

    // Grid: 2 floats per pixel -> 8 floats for 4 pixels, 32 B aligned.
    const float4* __restrict__ g4 = (const float4*)(grid + (size_t)p0 * 2u);
    float4 ga = g4[0];   // (x0,y0,x1,y1)
    float4 gb = g4[1];   // (x2,y2,x3,y3)

    float xs[4] = {ga.x, ga.z, gb.x, gb.z};
    float ys[4] = {ga.y, ga.w, gb.y, gb.w};

    float res[4];

    #pragma unroll
    for (int i = 0; i < 4; ++i) {
        float ix = fmaf(xs[i], 512.0f, 511.5f);
        float iy = fmaf(ys[i], 512.0f, 511.5f);
        float x0f = floorf(ix);
        float y0f = floorf(iy);
        float wx = ix - x0f;
        float wy = iy - y0f;
        int x0 = (int)x0f;
        int y0 = (int)y0f;

        bool xv0 = (unsigned)x0 < (unsigned)DIM;
        bool xv1 = (unsigned)(x0 + 1) < (unsigned)DIM;
        bool yv0 = (unsigned)y0 < (unsigned)DIM;
        bool yv1 = (unsigned)(y0 + 1) < (unsigned)DIM;

        // Aligned quad containing x0 (clamped into the image for addr safety).
        int xa = min(max(x0, 0) & ~3, DIM - 4);   // in [0, 1020]
        int d0 = x0 - xa;                         // 0..3 when x0 valid; -1 when x0==-1
        int i0 = min(max(d0, 0), 3);
        int i1 = min(max(d0 + 1, 0), 3);
        bool wrap = (d0 == 3) & xv1;              // x0+1 == xa+4 spills past quad

        int yc0 = min(max(y0, 0), DIM - 1);
        int yc1 = min(max(y0 + 1, 0), DIM - 1);
        const float* row0 = base + ((unsigned)yc0 << 10);
        const float* row1 = base + ((unsigned)yc1 << 10);

        float4 q0 = __ldg((const float4*)(row0 + xa));
        float4 q1 = __ldg((const float4*)(row1 + xa));

        // Predicated spill loads (only when wrap; address clamped = safe).
        int xe = min(x0 + 1, DIM - 1);
        float e0 = wrap ? __ldg(row0 + xe) : 0.0f;
        float e1 = wrap ? __ldg(row1 + xe) : 0.0f;

        float v00 = (xv0 & yv0) ? pick4(q0, i0) : 0.0f;
        float v10 = (xv0 & yv1) ? pick4(q1, i0) : 0.0f;
        float v01 = (xv1 & yv0) ? (wrap ? e0 : pick4(q0, i1)) : 0.0f;
        float v11 = (xv1 & yv1) ? (wrap ? e1 : pick4(q1, i1)) : 0.0f;

        float top = fmaf(v01 - v00, wx, v00);   // v00*(1-wx) + v01*wx
        float bot = fmaf(v11 - v10, wx, v10);
        res[i] = fmaf(bot - top, wy, top);
    }

    float4 o;
    o.x = res[0]; o.y = res[1]; o.z = res[2]; o.w = res[3];
    *(float4*)(out + (size_t)p0) = o;
}

extern "C" void kernel_launch(void* const* d_in, const int* in_sizes, int n_in,
                              void* d_out, int out_size)
{
    const float* img  = (const float*)d_in[0];   // source_depth
    const float* grid = (const float*)d_in[1];   // pr
    // d_in[2] (gt_map) unused.
    float* out = (float*)d_out;

    const unsigned threads = 256;
    const unsigned total_thr = TOTAL / 4u;       // 4 pixels per thread
    const unsigned blocks = (total_thr + threads - 1) / threads;
    esm_grid_sample_kernel<<<blocks, threads>>>(img, grid, out);
}